// round 15
// baseline (speedup 1.0000x reference)
#include <cuda_runtime.h>
#include <cstdint>

// MeanAggregator: out[b, :] = mean_{s<S} features[neigh_idx[b,s], :]
// B=50000, S=10, N=1e6, D=128 (fp32).
//
// Converged structure (R7/R9/R10/R11 A-Bs): ONE row per warp, one-shot
// blocks, 32 regs -> ~86% occupancy. Indices fetched with ONE lane-parallel
// coalesced LDG + SHFL.IDX distribution.
//
// This round: feature gathers carry an L2::evict_last cache-hint policy
// (createpolicy.fractional + ld.global.nc.L2::cache_hint.v4.f32 — the bare
// .L2::evict_last qualifier is 256-bit-only on sm_103a, which broke R12).
// Features are the only reused stream (~55MB duplicate touches of 256MB);
// retaining them targets the residual duplicate misses. Indices (__ldcs) and
// output (__stcs) stay evict-first.
//
// Each lane owns one float4 column: 32*16B = 512B = one full feature row per
// LDG wave, fully coalesced. Offsets are uint32 BYTE offsets (idx*512 < 2^32).
//
// Index dtype (int32 vs int64) detected inline: odd 32-bit words of the first
// 4 elements all zero iff little-endian int64 with values < 2^31.

#define AGG_B 50000
#define AGG_S 10
#define AGG_D 128
#define AGG_VEC (AGG_D / 4)   // 32 float4 per row == one per lane

__device__ __forceinline__ float4 ldg_evict_last_f4(const void* p,
                                                    unsigned long long pol)
{
    float4 v;
    asm volatile(
        "ld.global.nc.L2::cache_hint.v4.f32 {%0,%1,%2,%3}, [%4], %5;"
        : "=f"(v.x), "=f"(v.y), "=f"(v.z), "=f"(v.w)
        : "l"(p), "l"(pol));
    return v;
}

__global__ __launch_bounds__(128, 16) void mean_agg_kernel(
    const unsigned* __restrict__ idx_raw,     // [B,S] int32 OR int64 words
    const char* __restrict__ features,        // [N, 512B rows]
    float4* __restrict__ out)                 // [B, 32] as float4
{
    const int gtid = blockIdx.x * blockDim.x + threadIdx.x;
    const int row  = gtid >> 5;          // warp id == output row
    const int lane = gtid & 31;          // lane == float4 column
    if (row >= AGG_B) return;

    // L2 evict_last policy for the reused feature stream
    unsigned long long pol;
    asm("createpolicy.fractional.L2::evict_last.b64 %0, 1.0;" : "=l"(pol));

    // Inline dtype detection (one broadcast sector, L1-resident after warp 0)
    const unsigned w1 = __ldg(idx_raw + 1);
    const unsigned w3 = __ldg(idx_raw + 3);
    const unsigned w5 = __ldg(idx_raw + 5);
    const unsigned w7 = __ldg(idx_raw + 7);
    const bool is64 = ((w1 | w3 | w5 | w7) == 0u);

    // ONE lane-parallel coalesced index load, then shuffle-distribute.
    unsigned myw = 0;
    if (is64) {
        if (lane < 2 * AGG_S)
            myw = __ldcs(idx_raw + (size_t)row * (2 * AGG_S) + lane);
    } else {
        if (lane < AGG_S)
            myw = __ldcs(idx_raw + row * AGG_S + lane);
    }
    const int stride = is64 ? 2 : 1;     // word position of element s

    unsigned off[AGG_S];
#pragma unroll
    for (int s = 0; s < AGG_S; s++)
        off[s] = __shfl_sync(0xffffffffu, myw, s * stride) << 9;  // idx*512

    const char* fb = features + lane * 16;   // hoisted lane offset

    float4 acc = make_float4(0.f, 0.f, 0.f, 0.f);
#pragma unroll
    for (int s = 0; s < AGG_S; s++) {
        float4 v = ldg_evict_last_f4(fb + off[s], pol);
        acc.x += v.x; acc.y += v.y; acc.z += v.z; acc.w += v.w;
    }

    const float inv = 1.0f / (float)AGG_S;
    acc.x *= inv; acc.y *= inv; acc.z *= inv; acc.w *= inv;

    // Streaming store: write-once output must not evict feature lines
    __stcs(&out[row * AGG_VEC + lane], acc);
}

extern "C" void kernel_launch(void* const* d_in, const int* in_sizes, int n_in,
                              void* d_out, int out_size)
{
    const unsigned* neigh_idx = (const unsigned*)d_in[0];  // [B,S] i32/i64
    const char*     features  = (const char*)d_in[1];      // fp32 [N, D]
    float4*         out       = (float4*)d_out;            // fp32 [B, D]

    const int threads = 128;                       // 4 warps / block
    const int total_threads = AGG_B * 32;          // one warp per row
    const int blocks = (total_threads + threads - 1) / threads;   // 12500
    mean_agg_kernel<<<blocks, threads>>>(neigh_idx, features, out);
}

// round 17
// speedup vs baseline: 1.0183x; 1.0183x over previous
#include <cuda_runtime.h>
#include <cstdint>

// MeanAggregator: out[b, :] = mean_{s<S} features[neigh_idx[b,s], :]
// B=50000, S=10, N=1e6, D=128 (fp32).
//
// FINAL (converged over R7..R15 A/Bs):
//  - ONE row per warp, one-shot blocks: 32 regs -> ~86-91% occupancy.
//    Persistent loops (R9) and 2-rows/warp (R10) both regressed; occupancy
//    and natural block-retirement overlap dominate per-warp MLP.
//  - Indices: ONE lane-parallel coalesced LDG + SHFL.IDX distribution,
//    streaming (__ldcs) since read-once.
//  - Feature gathers: default-policy LDG.128; evict_last policy (R15) was
//    neutral -> default L2 replacement already captures duplicate-row reuse.
//  - Output: streaming __stcs (write-once must not evict feature lines).
//  - Each lane owns one float4 column: 32*16B = 512B = one full feature row
//    per LDG wave, fully coalesced. Offsets as uint32 BYTES (idx*512 < 2^32).
//  - Achieved ~5.85 TB/s (~74% of spec) = random-512B-gather DRAM ceiling;
//    traffic within ~6% of the 229MB compulsory floor.
//
// Index dtype (int32 vs int64) detected inline: odd 32-bit words of the first
// 4 elements all zero iff little-endian int64 with values < 2^31
// (false-positive P ~ 1e-24 for random int32 in [0,1e6)).

#define AGG_B 50000
#define AGG_S 10
#define AGG_D 128
#define AGG_VEC (AGG_D / 4)   // 32 float4 per row == one per lane

__global__ __launch_bounds__(128, 16) void mean_agg_kernel(
    const unsigned* __restrict__ idx_raw,     // [B,S] int32 OR int64 words
    const char* __restrict__ features,        // [N, 512B rows]
    float4* __restrict__ out)                 // [B, 32] as float4
{
    const int gtid = blockIdx.x * blockDim.x + threadIdx.x;
    const int row  = gtid >> 5;          // warp id == output row
    const int lane = gtid & 31;          // lane == float4 column
    if (row >= AGG_B) return;

    // Inline dtype detection (one broadcast sector, L1-resident after warp 0)
    const unsigned w1 = __ldg(idx_raw + 1);
    const unsigned w3 = __ldg(idx_raw + 3);
    const unsigned w5 = __ldg(idx_raw + 5);
    const unsigned w7 = __ldg(idx_raw + 7);
    const bool is64 = ((w1 | w3 | w5 | w7) == 0u);

    // ONE lane-parallel coalesced index load, then shuffle-distribute.
    unsigned myw = 0;
    if (is64) {
        if (lane < 2 * AGG_S)
            myw = __ldcs(idx_raw + (size_t)row * (2 * AGG_S) + lane);
    } else {
        if (lane < AGG_S)
            myw = __ldcs(idx_raw + row * AGG_S + lane);
    }
    const int stride = is64 ? 2 : 1;     // word position of element s

    unsigned off[AGG_S];
#pragma unroll
    for (int s = 0; s < AGG_S; s++)
        off[s] = __shfl_sync(0xffffffffu, myw, s * stride) << 9;  // idx*512

    const char* fb = features + lane * 16;   // hoisted lane offset

    float4 acc = make_float4(0.f, 0.f, 0.f, 0.f);
#pragma unroll
    for (int s = 0; s < AGG_S; s++) {
        float4 v = __ldg((const float4*)(fb + off[s]));
        acc.x += v.x; acc.y += v.y; acc.z += v.z; acc.w += v.w;
    }

    const float inv = 1.0f / (float)AGG_S;
    acc.x *= inv; acc.y *= inv; acc.z *= inv; acc.w *= inv;

    // Streaming store: write-once output must not evict feature lines
    __stcs(&out[row * AGG_VEC + lane], acc);
}

extern "C" void kernel_launch(void* const* d_in, const int* in_sizes, int n_in,
                              void* d_out, int out_size)
{
    const unsigned* neigh_idx = (const unsigned*)d_in[0];  // [B,S] i32/i64
    const char*     features  = (const char*)d_in[1];      // fp32 [N, D]
    float4*         out       = (float4*)d_out;            // fp32 [B, D]

    const int threads = 128;                       // 4 warps / block
    const int total_threads = AGG_B * 32;          // one warp per row
    const int blocks = (total_threads + threads - 1) / threads;   // 12500
    mean_agg_kernel<<<blocks, threads>>>(neigh_idx, features, out);
}